// round 16
// baseline (speedup 1.0000x reference)
#include <cuda_runtime.h>
#include <cuda_fp16.h>
#include <mma.h>
#include <math.h>
using namespace nvcuda;

constexpr int TYc=128, Bc=64, TXc=400, Hc=512, Cc=512, G4c=2048;
constexpr int NTc=1024;

// ---------------- device scratch ----------------
__device__ float g_pctx[(size_t)TXc*Bc*Cc];                 // fp32 key proj (no bias)
__device__ __align__(16) __half g_pvh[(size_t)TXc*Bc*Cc];   // fp16 value proj (no bias)
__device__ float g_xw  [(size_t)TYc*Bc*G4c];
__device__ float g_xwT [(size_t)TYc*G4c*Bc];
__device__ float g_bias4[G4c];
__device__ float g_sT[2][1024*Bc];
__device__ float g_hq2[2][Bc*Cc];
__device__ float g_acc[Bc*TXc];
__device__ float g_ctxbuf[(size_t)TYc*Bc*Cc];
__device__ float g_attbuf[(size_t)TYc*Bc*Cc];
__device__ volatile unsigned g_p1flag[64*8];
__device__ volatile unsigned g_hqflag[64*8];
__device__ volatile unsigned g_ackflag[64*8];

// pool1 smem layout (floats)
constexpr int P1_WHH=0;        // 32 x 524
constexpr int P1_WCB=16768;    // 8 x 1048
constexpr int P1_RED=25152;    // 17408
constexpr int P1_GATE=42560;   // 2048
constexpr int SMEM_FLOATS=44608;
// pool2 smem layout
constexpr int P2_U   =0;
constexpr int P2_WC  =512;
constexpr int P2_BATT=1024;
constexpr int P2_BV  =1536;
constexpr int P2_RATIO=2048;   // 16
constexpr int P2_E   =2064;    // 8x408
constexpr int P2_W   =5328;    // 8x408
constexpr int P2_RED =8592;    // 8x512

__device__ __forceinline__ float sigf(float x){ return 1.0f/(1.0f+__expf(-x)); }
__device__ __forceinline__ float tanh_acc(float x){
    float e=__expf(2.0f*fabsf(x));
    float r=1.0f-2.0f/(e+1.0f);
    return copysignf(r,x);
}
__device__ __forceinline__ float tanh_fast(float x){
    float r; asm("tanh.approx.f32 %0,%1;":"=f"(r):"f"(x)); return r;
}

// ---------------- tf32 tensor-core GEMM: C = A @ B^T (no bias), K=512 ------
// bid<800: pctx (fp32 out); else pv (fp16 out). tile 128x128, 8 warps.
__global__ void __launch_bounds__(256,1) tc_gemm(const float* __restrict__ Actx,
                        const float* __restrict__ Wc,const float* __restrict__ Wv){
    __shared__ float As[2][2560];   // [buf][128*20]
    __shared__ float Bs[2][2560];
    int bid=blockIdx.x;
    const float* Bm; float* Cout=nullptr; __half* Hout=nullptr;
    int bm,bn;
    if(bid<800){ Bm=Wc; Cout=g_pctx; bm=(bid>>2)*128; bn=(bid&3)*128; }
    else { int l=bid-800; Bm=Wv; Hout=g_pvh; bm=(l>>2)*128; bn=(l&3)*128; }
    const int tid=threadIdx.x, wid=tid>>5, lane=tid&31;
    const int wm=wid>>2, wn=wid&3;          // warp tile: 64(m) x 32(n)
    const int lrow=tid>>2, lk=(tid&3)*4;

    wmma::fragment<wmma::accumulator,16,16,8,float> acc[4][2];
#pragma unroll
    for(int i=0;i<4;i++)
#pragma unroll
        for(int j=0;j<2;j++) wmma::fill_fragment(acc[i][j],0.0f);

    float4 ra0,ra1,rb0,rb1;
    auto gload=[&](int c){
        ra0=*(const float4*)&Actx[(size_t)(bm+lrow)*512    + c*16 + lk];
        ra1=*(const float4*)&Actx[(size_t)(bm+64+lrow)*512 + c*16 + lk];
        rb0=*(const float4*)&Bm [(size_t)(bn+lrow)*512    + c*16 + lk];
        rb1=*(const float4*)&Bm [(size_t)(bn+64+lrow)*512 + c*16 + lk];
    };
    auto sstore=[&](int buf){
        *(float4*)&As[buf][lrow*20+lk]     =ra0;
        *(float4*)&As[buf][(64+lrow)*20+lk]=ra1;
        *(float4*)&Bs[buf][lrow*20+lk]     =rb0;
        *(float4*)&Bs[buf][(64+lrow)*20+lk]=rb1;
    };
    gload(0); sstore(0); __syncthreads();
    for(int c=0;c<32;c++){
        int buf=c&1;
        if(c<31) gload(c+1);
#pragma unroll
        for(int ks=0;ks<2;ks++){
            wmma::fragment<wmma::matrix_a,16,16,8,wmma::precision::tf32,wmma::row_major> a[4];
            wmma::fragment<wmma::matrix_b,16,16,8,wmma::precision::tf32,wmma::col_major> bfr[2];
#pragma unroll
            for(int i=0;i<4;i++){
                wmma::load_matrix_sync(a[i],&As[buf][(wm*64+i*16)*20+ks*8],20);
#pragma unroll
                for(int e=0;e<a[i].num_elements;e++) a[i].x[e]=wmma::__float_to_tf32(a[i].x[e]);
            }
#pragma unroll
            for(int j=0;j<2;j++){
                wmma::load_matrix_sync(bfr[j],&Bs[buf][(wn*32+j*16)*20+ks*8],20);
#pragma unroll
                for(int e=0;e<bfr[j].num_elements;e++) bfr[j].x[e]=wmma::__float_to_tf32(bfr[j].x[e]);
            }
#pragma unroll
            for(int i=0;i<4;i++)
#pragma unroll
                for(int j=0;j<2;j++) wmma::mma_sync(acc[i][j],a[i],bfr[j],acc[i][j]);
        }
        if(c<31){ __syncthreads(); sstore((c+1)&1); }
        __syncthreads();
    }
    if(Cout){
#pragma unroll
        for(int i=0;i<4;i++)
#pragma unroll
            for(int j=0;j<2;j++)
                wmma::store_matrix_sync(&Cout[(size_t)(bm+wm*64+i*16)*512 + bn+wn*32+j*16],
                                        acc[i][j],512,wmma::mem_row_major);
    } else {
        float* scr=&As[0][0]+wid*336;
#pragma unroll
        for(int i=0;i<4;i++)
#pragma unroll
            for(int j=0;j<2;j++){
                wmma::store_matrix_sync(scr,acc[i][j],20,wmma::mem_row_major);
                __syncwarp();
                int m0=bm+wm*64+i*16, n0=bn+wn*32+j*16;
#pragma unroll
                for(int q=0;q<8;q++){
                    int idx=q*32+lane, r=idx>>4, cc=idx&15;
                    Hout[(size_t)(m0+r)*512+n0+cc]=__float2half_rn(scr[r*20+cc]);
                }
                __syncwarp();
            }
    }
}

// ---------------- fp32 GEMM for xw (keeps LSTM path exact) -----------------
__global__ void xw_sgemm(const float* __restrict__ yemb,const float* __restrict__ Wih){
    const int K=512, N=2048;
    __shared__ float As[8][128], Bs[8][128];
    int l=blockIdx.x;
    int bm=(l>>4)*128, bn=(l&15)*128;
    int tid=threadIdx.x;
    int lr=tid>>1, lc=(tid&1)*4;
    int ty=tid>>4, tx=tid&15;
    float acc[8][8]={};
    const float* Ap=yemb+(size_t)(bm+lr)*K+lc;
    const float* Bp=Wih +(size_t)(bn+lr)*K+lc;
    float4 a4=*(const float4*)(Ap);
    float4 b4=*(const float4*)(Bp);
    for(int k0=0;k0<K;k0+=8){
        As[lc][lr]=a4.x; As[lc+1][lr]=a4.y; As[lc+2][lr]=a4.z; As[lc+3][lr]=a4.w;
        Bs[lc][lr]=b4.x; Bs[lc+1][lr]=b4.y; Bs[lc+2][lr]=b4.z; Bs[lc+3][lr]=b4.w;
        __syncthreads();
        if(k0+8<K){ a4=*(const float4*)(Ap+k0+8); b4=*(const float4*)(Bp+k0+8); }
#pragma unroll
        for(int kk=0;kk<8;kk++){
            float ar[8],br[8];
            *(float4*)&ar[0]=*(const float4*)&As[kk][ty*8];
            *(float4*)&ar[4]=*(const float4*)&As[kk][ty*8+4];
            *(float4*)&br[0]=*(const float4*)&Bs[kk][tx*8];
            *(float4*)&br[4]=*(const float4*)&Bs[kk][tx*8+4];
#pragma unroll
            for(int i=0;i<8;i++)
#pragma unroll
                for(int j=0;j<8;j++) acc[i][j]=fmaf(ar[i],br[j],acc[i][j]);
        }
        __syncthreads();
    }
#pragma unroll
    for(int i=0;i<8;i++){
        size_t m=bm+ty*8+i;
#pragma unroll
        for(int j=0;j<8;j+=4){
            int n=bn+tx*8+j;
            float4 o;
            o.x=acc[i][j+0]+g_bias4[n+0]; o.y=acc[i][j+1]+g_bias4[n+1];
            o.z=acc[i][j+2]+g_bias4[n+2]; o.w=acc[i][j+3]+g_bias4[n+3];
            *(float4*)&g_xw[m*(size_t)N+n]=o;
        }
    }
}

__global__ void transpose_xw(){
    __shared__ float tl[64][33];
    int j0=blockIdx.x*32, t=blockIdx.y;
    for(int f=threadIdx.x; f<2048; f+=256){ int b=f>>5, j=f&31;
        tl[b][j]=g_xw[((size_t)t*64+b)*2048 + j0+j]; }
    __syncthreads();
    for(int f=threadIdx.x; f<2048; f+=256){ int j=f>>6, b=f&63;
        g_xwT[(size_t)t*131072 + (size_t)(j0+j)*64 + b]=tl[b][j]; }
}

__global__ void init_state(const float* __restrict__ h0,const float* __restrict__ c0,
                           const float* __restrict__ cov,
                           const float* __restrict__ bi,const float* __restrict__ bh){
    int i=blockIdx.x*256+threadIdx.x;
    if(i<Bc*Hc){ int b=i>>9,u=i&511; g_sT[0][u*64+b]=h0[i]; g_sT[0][(512+u)*64+b]=c0[i]; }
    if(i<Bc*TXc) g_acc[i]=cov[i];
    if(i<G4c) g_bias4[i]=bi[i]+bh[i];
    if(i<64*8){ g_p1flag[i]=0; g_hqflag[i]=0; g_ackflag[i]=0; }
}

// ---------------- pipelined persistent decoder (bias-folded) ---------------
__global__ void __launch_bounds__(NTc,1)
decoder_persistent(const float* __restrict__ xmask,const float* __restrict__ ymask,
                   const float* __restrict__ W_hh,const float* __restrict__ W_comb,
                   const float* __restrict__ U_att,const float* __restrict__ W_cov,
                   const float* __restrict__ b_att,const float* __restrict__ bv_att,
                   float* __restrict__ o_hs,float* __restrict__ o_cs,
                   float* __restrict__ o_ss,
                   float* __restrict__ o_dists,float* __restrict__ o_Cs){
    extern __shared__ float sm[];
    const int tid=threadIdx.x, bk=blockIdx.x;
    const int wid=tid>>5, lane=tid&31;

    if(bk<64){
        // =================== POOL 1: A + B ===================
        const int bk1=bk;
        for(int f=tid;f<32*512;f+=NTc){ int j=f>>9,k=f&511;
            sm[P1_WHH + j*524 + k] =
                W_hh[(size_t)((j>>3)*512 + bk1*8 + (j&7))*512 + k]; }
        for(int f=tid;f<8*1024;f+=NTc){ int c=f>>10,k=f&1023;
            sm[P1_WCB + c*1048 + k] = W_comb[(size_t)(bk1*8+c)*1024 + k]; }
        __syncthreads();

        unsigned p1gen=0;
        for(int t=0;t<TYc;t++){
            const int ph=t&1;
            {
                const int ks=tid>>7, jg=(tid>>4)&7, bg=tid&15;
                const float* hT=g_sT[ph];
                float acc[4][4]={};
#pragma unroll 4
                for(int kk=0;kk<64;kk++){
                    int k=ks*64+kk;
                    float4 hv=*(const float4*)&hT[(size_t)k*64+bg*4];
#pragma unroll
                    for(int ji=0;ji<4;ji++){
                        float w=sm[P1_WHH + (jg*4+ji)*524 + k];
                        acc[ji][0]=fmaf(w,hv.x,acc[ji][0]);
                        acc[ji][1]=fmaf(w,hv.y,acc[ji][1]);
                        acc[ji][2]=fmaf(w,hv.z,acc[ji][2]);
                        acc[ji][3]=fmaf(w,hv.w,acc[ji][3]);
                    }
                }
#pragma unroll
                for(int ji=0;ji<4;ji++)
                    *(float4*)&sm[P1_RED + ks*2176 + (jg*4+ji)*68 + bg*4]
                        =*(float4*)&acc[ji][0];
            }
            __syncthreads();
            for(int v=tid;v<2048;v+=NTc){
                int j=v>>6, b=v&63;
                float s=0.f;
#pragma unroll
                for(int q=0;q<8;q++) s+=sm[P1_RED + q*2176 + j*68 + b];
                sm[P1_GATE + j*64 + b]=s;
            }
            __syncthreads();
            if(tid<512){
                int ui=tid>>6, b=tid&63;
                int u=bk1*8+ui;
                const float* xwT=&g_xwT[(size_t)t*131072];
                float gi=sm[P1_GATE+(0*8+ui)*64+b]+xwT[(size_t)(0*512+u)*64+b];
                float gf=sm[P1_GATE+(1*8+ui)*64+b]+xwT[(size_t)(1*512+u)*64+b];
                float gg=sm[P1_GATE+(2*8+ui)*64+b]+xwT[(size_t)(2*512+u)*64+b];
                float go=sm[P1_GATE+(3*8+ui)*64+b]+xwT[(size_t)(3*512+u)*64+b];
                float ho=g_sT[ph][u*64+b];
                float co=g_sT[ph][(512+u)*64+b];
                float c1=sigf(gf)*co+sigf(gi)*tanh_acc(gg);
                float h1=sigf(go)*tanh_acc(c1);
                float m=ymask[t*64+b];
                h1=m*h1+(1.0f-m)*ho;
                c1=m*c1+(1.0f-m)*co;
                g_sT[ph^1][u*64+b]=h1;
                g_sT[ph^1][(512+u)*64+b]=c1;
                size_t oo=((size_t)t*64+b)*512+u;
                o_hs[oo]=h1; o_ss[oo]=h1; o_cs[oo]=c1;
            }
            {
                ++p1gen;
                __syncthreads();
                if(tid==0){ __threadfence(); g_p1flag[bk1*8]=p1gen; }
                if(tid<64){ while(g_p1flag[tid*8]<p1gen){} }
                __syncthreads();
                if(tid==0) __threadfence();
                __syncthreads();
            }
            if(t>=2){
                if(tid<64){ while(g_ackflag[tid*8]<(unsigned)(t-1)){} }
                __syncthreads();
            }
            {
                const int ks=tid>>6, cl=(tid>>3)&7, bg=tid&7;
                const float* sT=g_sT[ph^1];
                float acc[8]={};
#pragma unroll 4
                for(int kk=0;kk<64;kk++){
                    int k=ks*64+kk;
                    float4 v0=*(const float4*)&sT[(size_t)k*64+bg*8];
                    float4 v1=*(const float4*)&sT[(size_t)k*64+bg*8+4];
                    float w=sm[P1_WCB + cl*1048 + k];
                    acc[0]=fmaf(w,v0.x,acc[0]); acc[1]=fmaf(w,v0.y,acc[1]);
                    acc[2]=fmaf(w,v0.z,acc[2]); acc[3]=fmaf(w,v0.w,acc[3]);
                    acc[4]=fmaf(w,v1.x,acc[4]); acc[5]=fmaf(w,v1.y,acc[5]);
                    acc[6]=fmaf(w,v1.z,acc[6]); acc[7]=fmaf(w,v1.w,acc[7]);
                }
                *(float4*)&sm[P1_RED + ks*520 + cl*64 + bg*8]  =*(float4*)&acc[0];
                *(float4*)&sm[P1_RED + ks*520 + cl*64 + bg*8+4]=*(float4*)&acc[4];
            }
            __syncthreads();
            if(tid<512){
                int c=tid>>6, b=tid&63;
                float s=0.f;
#pragma unroll
                for(int q=0;q<16;q++) s+=sm[P1_RED + q*520 + c*64 + b];
                g_hq2[ph][b*512 + bk1*8 + c]=s;
            }
            __syncthreads();
            if(tid==0){ __threadfence(); g_hqflag[bk1*8]=(unsigned)(t+1); }
        }
    } else {
        // =================== POOL 2: C + softmax + E (per-b local) =========
        const int b=bk-64;
        for(int f=tid;f<512;f+=NTc){
            sm[P2_U+f]=U_att[f]; sm[P2_WC+f]=W_cov[f];
            sm[P2_BATT+f]=b_att[f]; sm[P2_BV+f]=bv_att[f];
        }
        __syncthreads();

        for(int t=0;t<TYc;t++){
            const int ph=t&1;
            if(tid<64){ while(g_hqflag[tid*8]<(unsigned)(t+1)){} }
            __syncthreads();
            if(tid==0) __threadfence();
            __syncthreads();
            float hqr[16];
#pragma unroll
            for(int ii=0;ii<16;ii++)
                hqr[ii]=g_hq2[ph][b*512 + ii*32 + lane] + sm[P2_BATT + ii*32 + lane];
            const float* accp=&g_acc[b*400];
            for(int i=0;i<13;i++){
                int ts=wid+32*i;
                if(ts<400){
                    float cov=accp[ts];
                    float xm=xmask[ts*64+b];
                    const float* pc=&g_pctx[((size_t)ts*64+b)*512];
                    float a[8]={};
#pragma unroll
                    for(int ii=0;ii<16;ii++){
                        int c=ii*32+lane;
                        float arg=pc[c]+hqr[ii]+cov*sm[P2_WC+c];
                        a[ii>>1]=fmaf(tanh_fast(arg),sm[P2_U+c],a[ii>>1]);
                    }
#pragma unroll
                    for(int hh=0;hh<8;hh++){
                        float s=a[hh]*xm;
#pragma unroll
                        for(int o=16;o>0;o>>=1) s+=__shfl_xor_sync(0xffffffffu,s,o);
                        if(lane==0) sm[P2_E + hh*408 + ts]=s;
                    }
                }
            }
            __syncthreads();
            if(tid==0) g_ackflag[b*8]=(unsigned)(t+1);
            if(wid<8){
                const int hh=wid;
                const float* ep=&sm[P2_E + hh*408];
                float ev[13]; float mx=-3.4e38f;
#pragma unroll
                for(int i=0;i<13;i++){ int ts=lane+32*i;
                    float v=(ts<400)?ep[ts]:-3.4e38f; ev[i]=v; mx=fmaxf(mx,v); }
#pragma unroll
                for(int o=16;o>0;o>>=1) mx=fmaxf(mx,__shfl_xor_sync(0xffffffffu,mx,o));
                float sum=0.f;
#pragma unroll
                for(int i=0;i<13;i++){ int ts=lane+32*i;
                    if(ts<400){ float v=__expf(ev[i]-mx)*xmask[ts*64+b]; ev[i]=v; sum+=v; } }
#pragma unroll
                for(int o=16;o>0;o>>=1) sum+=__shfl_xor_sync(0xffffffffu,sum,o);
                float inv=1.0f/(sum+1e-6f);
                if(lane==0) sm[P2_RATIO+hh]=sum*inv;   // Σw (exact bias factor)
#pragma unroll
                for(int i=0;i<13;i++){ int ts=lane+32*i;
                    if(ts<400){
                        float w=ev[i]*inv;
                        sm[P2_W + hh*408 + ts]=w;
                        if(hh==0){
                            float a=g_acc[b*400+ts];
                            o_Cs[((size_t)t*64+b)*400+ts]=a;
                            o_dists[((size_t)t*64+b)*400+ts]=w;
                            g_acc[b*400+ts]=a+w;
                        }
                    } }
            }
            __syncthreads();
            {
                const int tq=tid>>7, cg=tid&127;
                const int c=cg*4, hl=cg>>4;
                const __half* pvp=&g_pvh[(size_t)b*512 + c];
                float a0=0.f,a1=0.f,a2=0.f,a3=0.f;
                int t0=tq*50;
#pragma unroll 5
                for(int tt=0;tt<50;tt++){
                    int ts=t0+tt;
                    uint2 raw=*(const uint2*)(pvp+(size_t)ts*32768);
                    float2 f01=__half22float2(*(__half2*)&raw.x);
                    float2 f23=__half22float2(*(__half2*)&raw.y);
                    float wv=sm[P2_W + hl*408 + ts];
                    a0=fmaf(f01.x,wv,a0); a1=fmaf(f01.y,wv,a1);
                    a2=fmaf(f23.x,wv,a2); a3=fmaf(f23.y,wv,a3);
                }
                sm[P2_RED + tq*512 + c+0]=a0;
                sm[P2_RED + tq*512 + c+1]=a1;
                sm[P2_RED + tq*512 + c+2]=a2;
                sm[P2_RED + tq*512 + c+3]=a3;
            }
            __syncthreads();
            if(tid<512){
                float s=0.f;
#pragma unroll
                for(int q=0;q<8;q++) s+=sm[P2_RED + q*512 + tid];
                s += sm[P2_BV+tid]*sm[P2_RATIO + (tid>>6)];   // folded bv_att
                g_ctxbuf[((size_t)t*64+b)*512 + tid]=s;
            }
            __syncthreads();
        }
    }
}

// ---------------- deferred: att = ctx @ W_concat^T ----------------
__global__ void att_gemm(const float* __restrict__ Wcat){
    const int K=512, N=512;
    __shared__ float As[8][128], Bs[8][128];
    int bm=blockIdx.y*128, bn=blockIdx.x*128;
    int tid=threadIdx.x;
    int lr=tid>>1, lc=(tid&1)*4;
    int ty=tid>>4, tx=tid&15;
    float acc[8][8]={};
    const float* Ap=g_ctxbuf+(size_t)(bm+lr)*K+lc;
    const float* Bp=Wcat+(size_t)(bn+lr)*K+lc;
    float4 a4=*(const float4*)(Ap);
    float4 b4=*(const float4*)(Bp);
    for(int k0=0;k0<K;k0+=8){
        As[lc][lr]=a4.x; As[lc+1][lr]=a4.y; As[lc+2][lr]=a4.z; As[lc+3][lr]=a4.w;
        Bs[lc][lr]=b4.x; Bs[lc+1][lr]=b4.y; Bs[lc+2][lr]=b4.z; Bs[lc+3][lr]=b4.w;
        __syncthreads();
        if(k0+8<K){ a4=*(const float4*)(Ap+k0+8); b4=*(const float4*)(Bp+k0+8); }
#pragma unroll
        for(int kk=0;kk<8;kk++){
            float ar[8],br[8];
            *(float4*)&ar[0]=*(const float4*)&As[kk][ty*8];
            *(float4*)&ar[4]=*(const float4*)&As[kk][ty*8+4];
            *(float4*)&br[0]=*(const float4*)&Bs[kk][tx*8];
            *(float4*)&br[4]=*(const float4*)&Bs[kk][tx*8+4];
#pragma unroll
            for(int i=0;i<8;i++)
#pragma unroll
                for(int j=0;j<8;j++) acc[i][j]=fmaf(ar[i],br[j],acc[i][j]);
        }
        __syncthreads();
    }
#pragma unroll
    for(int i=0;i<8;i++){
        size_t m=bm+ty*8+i;
#pragma unroll
        for(int j=0;j<8;j+=4){
            *(float4*)&g_attbuf[m*N+bn+tx*8+j]=*(float4*)&acc[i][j];
        }
    }
}

// ---------------- deferred LayerNorm ----------------
__global__ void ln_out(const float* __restrict__ lng,const float* __restrict__ lnb,
                       float* __restrict__ o_atts){
    __shared__ float red[16];
    int r=blockIdx.x, tid=threadIdx.x;
    int lane=tid&31, wd=tid>>5;
    float v0=g_attbuf[(size_t)r*512+tid];
    float v1=g_attbuf[(size_t)r*512+256+tid];
    float s=v0+v1;
#pragma unroll
    for(int o=16;o>0;o>>=1) s+=__shfl_xor_sync(0xffffffffu,s,o);
    if(lane==0) red[wd]=s;
    __syncthreads();
    float mu=0.f;
#pragma unroll
    for(int i=0;i<8;i++) mu+=red[i];
    mu*=(1.0f/512.0f);
    __syncthreads();
    float d0=v0-mu, d1=v1-mu;
    float s2=d0*d0+d1*d1;
#pragma unroll
    for(int o=16;o>0;o>>=1) s2+=__shfl_xor_sync(0xffffffffu,s2,o);
    if(lane==0) red[wd]=s2;
    __syncthreads();
    float var=0.f;
#pragma unroll
    for(int i=0;i<8;i++) var+=red[i];
    var*=(1.0f/512.0f);
    float inv=rsqrtf(var+1e-5f);
    o_atts[(size_t)r*512+tid]     =d0*inv*lng[tid]     +lnb[tid];
    o_atts[(size_t)r*512+256+tid] =d1*inv*lng[256+tid] +lnb[256+tid];
}

extern "C" void kernel_launch(void* const* d_in,const int* in_sizes,int n_in,
                              void* d_out,int out_size){
    const float* y_emb   =(const float*)d_in[0];
    const float* context =(const float*)d_in[1];
    const float* h0      =(const float*)d_in[2];
    const float* c0      =(const float*)d_in[3];
    const float* xmask   =(const float*)d_in[4];
    const float* ymask   =(const float*)d_in[5];
    const float* cov0    =(const float*)d_in[6];
    const float* W_ih    =(const float*)d_in[7];
    const float* W_hh    =(const float*)d_in[8];
    const float* b_ih    =(const float*)d_in[9];
    const float* b_hh    =(const float*)d_in[10];
    const float* Wc_att  =(const float*)d_in[11];
    const float* b_att   =(const float*)d_in[12];
    const float* Wv_att  =(const float*)d_in[13];
    const float* bv_att  =(const float*)d_in[14];
    const float* W_comb  =(const float*)d_in[15];
    const float* U_att   =(const float*)d_in[16];
    const float* W_cov   =(const float*)d_in[17];
    const float* W_concat=(const float*)d_in[18];
    const float* ln_g    =(const float*)d_in[19];
    const float* ln_b    =(const float*)d_in[20];

    float* out    =(float*)d_out;
    float* o_hs   =out;
    float* o_cs   =o_hs+(size_t)TYc*Bc*Hc;
    float* o_ss   =o_cs+(size_t)TYc*Bc*Hc;
    float* o_atts =o_ss+(size_t)TYc*Bc*Hc;
    float* o_dists=o_atts+(size_t)TYc*Bc*Cc;
    float* o_Cs   =o_dists+(size_t)TYc*Bc*TXc;

    init_state<<<128,256>>>(h0,c0,cov0,b_ih,b_hh);
    tc_gemm<<<1600,256>>>(context,Wc_att,Wv_att);
    xw_sgemm<<<1024,256>>>(y_emb,W_ih);
    transpose_xw<<<dim3(64,128),256>>>();

    cudaFuncSetAttribute(decoder_persistent,
        cudaFuncAttributeMaxDynamicSharedMemorySize, SMEM_FLOATS*4);
    decoder_persistent<<<128,NTc,SMEM_FLOATS*4>>>(xmask,ymask,W_hh,W_comb,U_att,W_cov,
        b_att,bv_att,o_hs,o_cs,o_ss,o_dists,o_Cs);

    att_gemm<<<dim3(4,64),256>>>(W_concat);
    ln_out<<<TYc*Bc,256>>>(ln_g,ln_b,o_atts);
}